// round 13
// baseline (speedup 1.0000x reference)
#include <cuda_runtime.h>
#include <cuda_fp16.h>
#include <cstdint>

// out[b, de] = sum_k w[b,k] * A[k, de], A diagonal (de % 257 == 0) zeroed for all k.
// W: (2048, 32) f32   A: (32, 65536) f32   Out: (2048, 65536) f32
//
// fp16 HMMA (m16n8k16, fp32 accum), permuted de->fragment mapping, v8 stores,
// 4 CTAs/SM:
//   de_local = 32q + 8t + 2u + v  stored at frag (4q+u), B-col (2t+v)
//   => thread's accumulators across a frag-quad = 8 contiguous de per row,
//   st.global.cs.v8.b32 = 8 full 128B lines per instruction, no staging.
//   B-fragments reloaded per m-group to fit 64 regs -> 32 warps/SM for store MLP.

#define DE   65536
#define KD   32
#define TDE  128     // de per CTA
#define TB   256     // batch per CTA
#define NB   2048
#define ASTRIDE 20   // uint32 row stride for A tile (conflict-free LDS.32)

#define SM_TOTAL (TDE * ASTRIDE * 4)   // 10240 bytes: A tile only

static __device__ __forceinline__ uint32_t pack_h2(float e0, float e1) {
    __half2 h = __floats2half2_rn(e0, e1);
    return *(uint32_t*)&h;
}

static __device__ __forceinline__ void mma16816(float* d, const uint32_t* a,
                                                uint32_t b0, uint32_t b1) {
    asm volatile(
        "mma.sync.aligned.m16n8k16.row.col.f32.f16.f16.f32 "
        "{%0,%1,%2,%3}, {%4,%5,%6,%7}, {%8,%9}, {%0,%1,%2,%3};"
        : "+f"(d[0]), "+f"(d[1]), "+f"(d[2]), "+f"(d[3])
        : "r"(a[0]), "r"(a[1]), "r"(a[2]), "r"(a[3]), "r"(b0), "r"(b1));
}

static __device__ __forceinline__ void stg_v8(float* p,
                                              float a0, float a1, float a2, float a3,
                                              float a4, float a5, float a6, float a7) {
    asm volatile(
        "st.global.cs.v8.b32 [%0], {%1,%2,%3,%4,%5,%6,%7,%8};"
        :: "l"(p),
           "r"(__float_as_uint(a0)), "r"(__float_as_uint(a1)),
           "r"(__float_as_uint(a2)), "r"(__float_as_uint(a3)),
           "r"(__float_as_uint(a4)), "r"(__float_as_uint(a5)),
           "r"(__float_as_uint(a6)), "r"(__float_as_uint(a7))
        : "memory");
}

__global__ __launch_bounds__(256, 4)
void explainer_hmma(const float* __restrict__ w,
                    const float* __restrict__ A,
                    float* __restrict__ out) {
    extern __shared__ char smem[];
    uint32_t* Ah = (uint32_t*)smem;

    const int tid = threadIdx.x;
    const int de0 = blockIdx.x * TDE;
    const int b0  = blockIdx.y * TB;

    // ---- Load A tile: 128 de x 16 k-pairs, fp16 packed, diagonal masked ----
    // Slot permutation: de = 32q + 8t + 2u + v  ->  slot_row = 32q + 8u + 2t + v
    #pragma unroll
    for (int i = 0; i < 8; i++) {
        int idx = tid + i * 256;        // 0..2047
        int p   = idx >> 7;             // k-pair 0..15
        int de  = idx & 127;
        int k0  = p << 1;
        float v0 = A[(size_t)k0 * DE + de0 + de];
        float v1 = A[(size_t)(k0 + 1) * DE + de0 + de];
        if (((de0 + de) % 257) == 0) { v0 = 0.0f; v1 = 0.0f; }
        int q = de >> 5;
        int t = (de >> 3) & 3;
        int u = (de >> 1) & 3;
        int v = de & 1;
        int slot = 32 * q + 8 * u + 2 * t + v;
        Ah[slot * ASTRIDE + p] = pack_h2(v0, v1);
    }

    // ---- W fragments in registers: warp covers 32 batches (2 m16 groups) ----
    const int warp = tid >> 5;
    const int lane = tid & 31;
    const int qr = lane >> 2;   // 0..7
    const int qc = lane & 3;    // 0..3
    const int mb = b0 + warp * 32;

    uint32_t whi[2][2][4];      // [m-group][k-step][a-reg]
    #pragma unroll
    for (int g = 0; g < 2; g++) {
        #pragma unroll
        for (int s = 0; s < 2; s++) {
            #pragma unroll
            for (int h = 0; h < 2; h++) {
                #pragma unroll
                for (int rr = 0; rr < 2; rr++) {
                    int row = mb + g * 16 + qr + rr * 8;
                    int kk  = s * 16 + 2 * qc + h * 8;
                    float2 v = *(const float2*)&w[(size_t)row * KD + kk];
                    whi[g][s][rr + 2 * h] = pack_h2(v.x, v.y);
                }
            }
        }
    }
    __syncthreads();

    // ---- Main loop: 4 frag-quads of 32 de, B-frags reloaded per m-group ----
    #pragma unroll 1
    for (int q = 0; q < 4; q++) {
        #pragma unroll
        for (int g = 0; g < 2; g++) {
            float dd[4][4];
            #pragma unroll
            for (int u = 0; u < 4; u++) {
                const uint32_t* ar = &Ah[(32 * q + 8 * u + qr) * ASTRIDE];
                uint32_t b0r = ar[qc],     b1r = ar[qc + 4];
                uint32_t b2r = ar[8 + qc], b3r = ar[12 + qc];
                dd[u][0] = 0.f; dd[u][1] = 0.f; dd[u][2] = 0.f; dd[u][3] = 0.f;
                mma16816(dd[u], whi[g][0], b0r, b1r);   // k-step 0
                mma16816(dd[u], whi[g][1], b2r, b3r);   // k-step 1
            }

            // Rows qr and qr+8: 8 contiguous de starting at 32q + 8qc
            size_t r0 = (size_t)(mb + g * 16 + qr);
            float* p0 = out + r0 * DE + de0 + 32 * q + 8 * qc;
            stg_v8(p0, dd[0][0], dd[0][1], dd[1][0], dd[1][1],
                       dd[2][0], dd[2][1], dd[3][0], dd[3][1]);
            float* p1 = out + (r0 + 8) * DE + de0 + 32 * q + 8 * qc;
            stg_v8(p1, dd[0][2], dd[0][3], dd[1][2], dd[1][3],
                       dd[2][2], dd[2][3], dd[3][2], dd[3][3]);
        }
    }
}

extern "C" void kernel_launch(void* const* d_in, const int* in_sizes, int n_in,
                              void* d_out, int out_size) {
    const float* w = (const float*)d_in[0];   // batch_weights (2048, 32)
    const float* A = (const float*)d_in[1];   // archs (32, 256, 256)
    float* out = (float*)d_out;               // (2048, 256, 256) f32

    cudaFuncSetAttribute(explainer_hmma, cudaFuncAttributeMaxDynamicSharedMemorySize,
                         SM_TOTAL);
    dim3 grid(DE / TDE, NB / TB);             // (512, 8)
    explainer_hmma<<<grid, 256, SM_TOTAL>>>(w, A, out);
}

// round 14
// speedup vs baseline: 1.3138x; 1.3138x over previous
#include <cuda_runtime.h>
#include <cuda_fp16.h>
#include <cstdint>

// out[b, de] = sum_k w[b,k] * A[k, de], A diagonal (de % 257 == 0) zeroed for all k.
// W: (2048, 32) f32   A: (32, 65536) f32   Out: (2048, 65536) f32
//
// fp16 HMMA (m16n8k16, fp32 accum), permuted de->fragment mapping, v8 stores.
//   de_local = 32q + 8t + 2u + v  stored at frag (4q+u), B-col (2t+v)
//   => thread's accumulators across a frag-quad = 8 contiguous de per row:
//   st.global.cs.v8.b32 = 8 full 128B lines per instruction, no staging.
//   CTA: 256 batch x 256 de (8 quads), 8 warps; b-frags loaded once per quad
//   and reused across both m-groups; quad loop unrolled 2x for latency overlap.
//   3 CTAs/SM (<=84 regs), grid 2048.

#define DE   65536
#define KD   32
#define TDE  256     // de per CTA (8 quads)
#define TB   256     // batch per CTA
#define NB   2048
#define NQ   (TDE / 32)
#define ASTRIDE 20   // uint32 row stride for A tile (conflict-free LDS.32)

#define SM_TOTAL (TDE * ASTRIDE * 4)   // 20480 bytes: A tile only

static __device__ __forceinline__ uint32_t pack_h2(float e0, float e1) {
    __half2 h = __floats2half2_rn(e0, e1);
    return *(uint32_t*)&h;
}

static __device__ __forceinline__ void mma16816(float* d, const uint32_t* a,
                                                uint32_t b0, uint32_t b1) {
    asm volatile(
        "mma.sync.aligned.m16n8k16.row.col.f32.f16.f16.f32 "
        "{%0,%1,%2,%3}, {%4,%5,%6,%7}, {%8,%9}, {%0,%1,%2,%3};"
        : "+f"(d[0]), "+f"(d[1]), "+f"(d[2]), "+f"(d[3])
        : "r"(a[0]), "r"(a[1]), "r"(a[2]), "r"(a[3]), "r"(b0), "r"(b1));
}

static __device__ __forceinline__ void stg_v8(float* p,
                                              float a0, float a1, float a2, float a3,
                                              float a4, float a5, float a6, float a7) {
    asm volatile(
        "st.global.cs.v8.b32 [%0], {%1,%2,%3,%4,%5,%6,%7,%8};"
        :: "l"(p),
           "r"(__float_as_uint(a0)), "r"(__float_as_uint(a1)),
           "r"(__float_as_uint(a2)), "r"(__float_as_uint(a3)),
           "r"(__float_as_uint(a4)), "r"(__float_as_uint(a5)),
           "r"(__float_as_uint(a6)), "r"(__float_as_uint(a7))
        : "memory");
}

__global__ __launch_bounds__(256, 3)
void explainer_hmma(const float* __restrict__ w,
                    const float* __restrict__ A,
                    float* __restrict__ out) {
    extern __shared__ char smem[];
    uint32_t* Ah = (uint32_t*)smem;

    const int tid = threadIdx.x;
    const int de0 = blockIdx.x * TDE;
    const int b0  = blockIdx.y * TB;

    // ---- Load A tile: 256 de x 16 k-pairs, fp16 packed, diagonal masked ----
    // Slot permutation: de = 32q + 8t + 2u + v  ->  slot_row = 32q + 8u + 2t + v
    #pragma unroll
    for (int i = 0; i < 16; i++) {
        int idx = tid + i * 256;        // 0..4095
        int p   = idx >> 8;             // k-pair 0..15
        int de  = idx & 255;
        int k0  = p << 1;
        float v0 = A[(size_t)k0 * DE + de0 + de];
        float v1 = A[(size_t)(k0 + 1) * DE + de0 + de];
        if (((de0 + de) % 257) == 0) { v0 = 0.0f; v1 = 0.0f; }
        int q = de >> 5;
        int t = (de >> 3) & 3;
        int u = (de >> 1) & 3;
        int v = de & 1;
        int slot = 32 * q + 8 * u + 2 * t + v;
        Ah[slot * ASTRIDE + p] = pack_h2(v0, v1);
    }

    // ---- W fragments in registers: warp covers 32 batches (2 m16 groups) ----
    const int warp = tid >> 5;
    const int lane = tid & 31;
    const int qr = lane >> 2;   // 0..7
    const int qc = lane & 3;    // 0..3
    const int mb = b0 + warp * 32;

    uint32_t whi[2][2][4];      // [m-group][k-step][a-reg]
    #pragma unroll
    for (int g = 0; g < 2; g++) {
        #pragma unroll
        for (int s = 0; s < 2; s++) {
            #pragma unroll
            for (int h = 0; h < 2; h++) {
                #pragma unroll
                for (int rr = 0; rr < 2; rr++) {
                    int row = mb + g * 16 + qr + rr * 8;
                    int kk  = s * 16 + 2 * qc + h * 8;
                    float2 v = *(const float2*)&w[(size_t)row * KD + kk];
                    whi[g][s][rr + 2 * h] = pack_h2(v.x, v.y);
                }
            }
        }
    }
    __syncthreads();

    // ---- Main loop: 8 frag-quads of 32 de; b-frags loaded once per quad ----
    #pragma unroll 2
    for (int q = 0; q < NQ; q++) {
        uint32_t bq[4][4];
        #pragma unroll
        for (int u = 0; u < 4; u++) {
            const uint32_t* ar = &Ah[(32 * q + 8 * u + qr) * ASTRIDE];
            bq[u][0] = ar[qc];     bq[u][1] = ar[qc + 4];
            bq[u][2] = ar[8 + qc]; bq[u][3] = ar[12 + qc];
        }

        #pragma unroll
        for (int g = 0; g < 2; g++) {
            float dd[4][4];
            #pragma unroll
            for (int u = 0; u < 4; u++) {
                dd[u][0] = 0.f; dd[u][1] = 0.f; dd[u][2] = 0.f; dd[u][3] = 0.f;
                mma16816(dd[u], whi[g][0], bq[u][0], bq[u][1]);   // k-step 0
                mma16816(dd[u], whi[g][1], bq[u][2], bq[u][3]);   // k-step 1
            }

            // Rows qr and qr+8: 8 contiguous de starting at 32q + 8qc
            size_t r0 = (size_t)(mb + g * 16 + qr);
            float* p0 = out + r0 * DE + de0 + 32 * q + 8 * qc;
            stg_v8(p0, dd[0][0], dd[0][1], dd[1][0], dd[1][1],
                       dd[2][0], dd[2][1], dd[3][0], dd[3][1]);
            float* p1 = out + (r0 + 8) * DE + de0 + 32 * q + 8 * qc;
            stg_v8(p1, dd[0][2], dd[0][3], dd[1][2], dd[1][3],
                       dd[2][2], dd[2][3], dd[3][2], dd[3][3]);
        }
    }
}

extern "C" void kernel_launch(void* const* d_in, const int* in_sizes, int n_in,
                              void* d_out, int out_size) {
    const float* w = (const float*)d_in[0];   // batch_weights (2048, 32)
    const float* A = (const float*)d_in[1];   // archs (32, 256, 256)
    float* out = (float*)d_out;               // (2048, 256, 256) f32

    cudaFuncSetAttribute(explainer_hmma, cudaFuncAttributeMaxDynamicSharedMemorySize,
                         SM_TOTAL);
    dim3 grid(DE / TDE, NB / TB);             // (256, 8)
    explainer_hmma<<<grid, 256, SM_TOTAL>>>(w, A, out);
}

// round 15
// speedup vs baseline: 1.3786x; 1.0493x over previous
#include <cuda_runtime.h>
#include <cuda_fp16.h>
#include <cstdint>

// out[b, de] = sum_k w[b,k] * A[k, de], A diagonal (de % 257 == 0) zeroed for all k.
// W: (2048, 32) f32   A: (32, 65536) f32   Out: (2048, 65536) f32
//
// fp16 HMMA (m16n8k16, fp32 accum), permuted de->fragment mapping, v8 stores.
//   de_local = 32q + 8t + 2u + v  stored at frag (4q+u), B-col (2t+v)
//   => thread's accumulators across a frag-quad = 8 contiguous de per row:
//   st.global.cs.v8.b32 = 8 full 128B lines per instruction, no staging.
//   CTA: 128 batch x 128 de, 128 threads (4 warps); warp-tile identical to the
//   91us design (32 batch x 128 de, bq once per quad). 7 CTAs/SM = 28 warps
//   for store MLP. Vectorized LDG.128 A-tile prologue.

#define DE   65536
#define KD   32
#define TDE  128     // de per CTA (4 quads)
#define TB   128     // batch per CTA (4 warps x 32)
#define NB   2048
#define ASTRIDE 20   // uint32 row stride for A tile (conflict-free LDS.32)

static __device__ __forceinline__ uint32_t pack_h2(float e0, float e1) {
    __half2 h = __floats2half2_rn(e0, e1);
    return *(uint32_t*)&h;
}

static __device__ __forceinline__ void mma16816(float* d, const uint32_t* a,
                                                uint32_t b0, uint32_t b1) {
    asm volatile(
        "mma.sync.aligned.m16n8k16.row.col.f32.f16.f16.f32 "
        "{%0,%1,%2,%3}, {%4,%5,%6,%7}, {%8,%9}, {%0,%1,%2,%3};"
        : "+f"(d[0]), "+f"(d[1]), "+f"(d[2]), "+f"(d[3])
        : "r"(a[0]), "r"(a[1]), "r"(a[2]), "r"(a[3]), "r"(b0), "r"(b1));
}

static __device__ __forceinline__ void stg_v8(float* p,
                                              float a0, float a1, float a2, float a3,
                                              float a4, float a5, float a6, float a7) {
    asm volatile(
        "st.global.cs.v8.b32 [%0], {%1,%2,%3,%4,%5,%6,%7,%8};"
        :: "l"(p),
           "r"(__float_as_uint(a0)), "r"(__float_as_uint(a1)),
           "r"(__float_as_uint(a2)), "r"(__float_as_uint(a3)),
           "r"(__float_as_uint(a4)), "r"(__float_as_uint(a5)),
           "r"(__float_as_uint(a6)), "r"(__float_as_uint(a7))
        : "memory");
}

__global__ __launch_bounds__(128, 7)
void explainer_hmma(const float* __restrict__ w,
                    const float* __restrict__ A,
                    float* __restrict__ out) {
    __shared__ uint32_t Ah[TDE * ASTRIDE];   // 10240 B

    const int tid = threadIdx.x;
    const int de0 = blockIdx.x * TDE;
    const int b0  = blockIdx.y * TB;

    // ---- Load A tile: 128 de x 16 k-pairs; vectorized LDG.128 along de ----
    // Thread t: de group (t&31)*4, k-pairs 4*(t>>5)..+3. Coalesced 512B/warp-instr.
    // Slot permutation: de = 32q + 8t2 + 2u + v -> slot_row = 32q + 8u + 2t2 + v.
    {
        const int deg = (tid & 31) << 2;   // 4 consecutive de
        const int pp0 = (tid >> 5) << 2;   // 4 k-pairs
        #pragma unroll
        for (int pi = 0; pi < 4; pi++) {
            int p  = pp0 + pi;
            int k0 = p << 1;
            float4 r0 = *(const float4*)&A[(size_t)k0 * DE + de0 + deg];
            float4 r1 = *(const float4*)&A[(size_t)(k0 + 1) * DE + de0 + deg];
            float v0[4] = {r0.x, r0.y, r0.z, r0.w};
            float v1[4] = {r1.x, r1.y, r1.z, r1.w};
            #pragma unroll
            for (int j = 0; j < 4; j++) {
                int de = deg + j;
                if (((de0 + de) % 257) == 0) { v0[j] = 0.0f; v1[j] = 0.0f; }
                int q = de >> 5;
                int t2 = (de >> 3) & 3;
                int u = (de >> 1) & 3;
                int v = de & 1;
                int slot = 32 * q + 8 * u + 2 * t2 + v;
                Ah[slot * ASTRIDE + p] = pack_h2(v0[j], v1[j]);
            }
        }
    }

    // ---- W fragments in registers: warp covers 32 batches (2 m16 groups) ----
    const int warp = tid >> 5;
    const int lane = tid & 31;
    const int qr = lane >> 2;   // 0..7
    const int qc = lane & 3;    // 0..3
    const int mb = b0 + warp * 32;

    uint32_t whi[2][2][4];      // [m-group][k-step][a-reg]
    #pragma unroll
    for (int g = 0; g < 2; g++) {
        #pragma unroll
        for (int s = 0; s < 2; s++) {
            #pragma unroll
            for (int h = 0; h < 2; h++) {
                #pragma unroll
                for (int rr = 0; rr < 2; rr++) {
                    int row = mb + g * 16 + qr + rr * 8;
                    int kk  = s * 16 + 2 * qc + h * 8;
                    float2 v = *(const float2*)&w[(size_t)row * KD + kk];
                    whi[g][s][rr + 2 * h] = pack_h2(v.x, v.y);
                }
            }
        }
    }
    __syncthreads();

    // ---- Main loop: 4 frag-quads of 32 de; b-frags loaded once per quad ----
    #pragma unroll 1
    for (int q = 0; q < 4; q++) {
        uint32_t bq[4][4];
        #pragma unroll
        for (int u = 0; u < 4; u++) {
            const uint32_t* ar = &Ah[(32 * q + 8 * u + qr) * ASTRIDE];
            bq[u][0] = ar[qc];     bq[u][1] = ar[qc + 4];
            bq[u][2] = ar[8 + qc]; bq[u][3] = ar[12 + qc];
        }

        #pragma unroll
        for (int g = 0; g < 2; g++) {
            float dd[4][4];
            #pragma unroll
            for (int u = 0; u < 4; u++) {
                dd[u][0] = 0.f; dd[u][1] = 0.f; dd[u][2] = 0.f; dd[u][3] = 0.f;
                mma16816(dd[u], whi[g][0], bq[u][0], bq[u][1]);   // k-step 0
                mma16816(dd[u], whi[g][1], bq[u][2], bq[u][3]);   // k-step 1
            }

            // Rows qr and qr+8: 8 contiguous de starting at 32q + 8qc
            size_t r0 = (size_t)(mb + g * 16 + qr);
            float* p0 = out + r0 * DE + de0 + 32 * q + 8 * qc;
            stg_v8(p0, dd[0][0], dd[0][1], dd[1][0], dd[1][1],
                       dd[2][0], dd[2][1], dd[3][0], dd[3][1]);
            float* p1 = out + (r0 + 8) * DE + de0 + 32 * q + 8 * qc;
            stg_v8(p1, dd[0][2], dd[0][3], dd[1][2], dd[1][3],
                       dd[2][2], dd[2][3], dd[3][2], dd[3][3]);
        }
    }
}

extern "C" void kernel_launch(void* const* d_in, const int* in_sizes, int n_in,
                              void* d_out, int out_size) {
    const float* w = (const float*)d_in[0];   // batch_weights (2048, 32)
    const float* A = (const float*)d_in[1];   // archs (32, 256, 256)
    float* out = (float*)d_out;               // (2048, 256, 256) f32

    dim3 grid(DE / TDE, NB / TB);             // (512, 16)
    explainer_hmma<<<grid, 128>>>(w, A, out);
}